// round 1
// baseline (speedup 1.0000x reference)
#include <cuda_runtime.h>

// Problem constants (fixed shapes for this problem instance)
#define HH     450          // hidden size
#define HH2    900          // 2*H
#define NM     6000         // messages
#define NNODE  4000         // nodes
#define KN     6            // max neighbors
#define NB     256          // batch (roots)
#define NDEPTH 15

// ---------------- scratch (device globals; no allocation allowed) -----------
__device__ float g_x  [NM * HH];
__device__ float g_xz [NM * HH];
__device__ float g_xr [NM * HH];
__device__ float g_xh [NM * HH];
__device__ float g_hA [NM * HH];
__device__ float g_hB [NM * HH];
__device__ float g_hU [NM * HH];
__device__ float g_sh [NM * HH];
__device__ float g_sg [NM * HH];
__device__ float g_root[NB * HH2];
__device__ float g_d1 [NB * HH];
__device__ float g_d2 [NB * HH];

// ---------------- math helpers ----------------------------------------------
__device__ __forceinline__ float sigmoid_(float t) {
    return 1.0f / (1.0f + __expf(-t));
}
__device__ __forceinline__ float tanh_(float t) {
    t = fminf(fmaxf(t, -12.0f), 12.0f);
    float e = __expf(2.0f * t);
    return (e - 1.0f) / (e + 1.0f);
}

// ---------------- generic SGEMM: C = A[MxK] * B^T (+bias) -------------------
// B is torch-style [N, K] row-major with row stride ldb and column offset boff.
// EPI: 0 = none, 1 = leaky_relu(0.1)
#define BM 64
#define BN 64
#define BK 16

template <int EPI>
__global__ __launch_bounds__(256)
void gemm_nt(const float* __restrict__ A, int lda,
             const float* __restrict__ Bw, int ldb, int boff,
             const float* __restrict__ bias,
             float* __restrict__ C,
             int Mv, int Nv, int Kv)
{
    __shared__ float As[BK][BM + 4];
    __shared__ float Bs[BK][BN + 4];

    const int bm = blockIdx.y * BM;
    const int bn = blockIdx.x * BN;
    const int tid = threadIdx.x;
    const int tx = tid & 15;
    const int ty = tid >> 4;

    float acc[4][4] = {};

    const int ar  = tid >> 2;        // 0..63 (row within tile)
    const int ac4 = (tid & 3) * 4;   // 0,4,8,12 (k within tile)

    for (int k0 = 0; k0 < Kv; k0 += BK) {
        #pragma unroll
        for (int u = 0; u < 4; u++) {
            int kk = ac4 + u;
            int row = bm + ar, col = k0 + kk;
            float v = 0.0f;
            if (row < Mv && col < Kv) v = A[row * lda + col];
            As[kk][ar] = v;
        }
        #pragma unroll
        for (int u = 0; u < 4; u++) {
            int kk = ac4 + u;
            int row = bn + ar, col = k0 + kk;
            float v = 0.0f;
            if (row < Nv && col < Kv) v = Bw[row * ldb + boff + col];
            Bs[kk][ar] = v;
        }
        __syncthreads();

        #pragma unroll
        for (int kk = 0; kk < BK; kk++) {
            float4 a4 = *reinterpret_cast<const float4*>(&As[kk][ty * 4]);
            float4 b4 = *reinterpret_cast<const float4*>(&Bs[kk][tx * 4]);
            float a[4] = {a4.x, a4.y, a4.z, a4.w};
            float b[4] = {b4.x, b4.y, b4.z, b4.w};
            #pragma unroll
            for (int i = 0; i < 4; i++)
                #pragma unroll
                for (int j = 0; j < 4; j++)
                    acc[i][j] = fmaf(a[i], b[j], acc[i][j]);
        }
        __syncthreads();
    }

    #pragma unroll
    for (int i = 0; i < 4; i++) {
        int row = bm + ty * 4 + i;
        if (row >= Mv) continue;
        #pragma unroll
        for (int j = 0; j < 4; j++) {
            int col = bn + tx * 4 + j;
            if (col >= Nv) continue;
            float v = acc[i][j];
            if (bias) v += bias[col];
            if (EPI == 1) v = (v > 0.0f) ? v : 0.1f * v;
            C[row * Nv + col] = v;
        }
    }
}

// ---------------- fused dual-GEMM GRU update --------------------------------
// acc1 = sum_h  @ Wz2^T  (Wz row stride 900, col offset 450)
// acc2 = sum_gh @ Wh2^T  (Wh row stride 900, col offset 450)
// h_new = ((1-z)*sum_h + z*tanh(xh+acc2)) with z = sigmoid(xz+acc1); row 0 = 0
__global__ __launch_bounds__(256)
void update_k(const float* __restrict__ sumh, const float* __restrict__ sumgh,
              const float* __restrict__ Wz,  const float* __restrict__ Wh,
              const float* __restrict__ xz,  const float* __restrict__ xh,
              float* __restrict__ hout)
{
    __shared__ float As1[BK][BM + 4];
    __shared__ float As2[BK][BM + 4];
    __shared__ float Bs1[BK][BN + 4];
    __shared__ float Bs2[BK][BN + 4];

    const int bm = blockIdx.y * BM;
    const int bn = blockIdx.x * BN;
    const int tid = threadIdx.x;
    const int tx = tid & 15;
    const int ty = tid >> 4;

    float acc1[4][4] = {};
    float acc2[4][4] = {};

    const int ar  = tid >> 2;
    const int ac4 = (tid & 3) * 4;

    for (int k0 = 0; k0 < HH; k0 += BK) {
        #pragma unroll
        for (int u = 0; u < 4; u++) {
            int kk = ac4 + u;
            int row = bm + ar, col = k0 + kk;
            float v1 = 0.0f, v2 = 0.0f;
            if (row < NM && col < HH) {
                v1 = sumh [row * HH + col];
                v2 = sumgh[row * HH + col];
            }
            As1[kk][ar] = v1;
            As2[kk][ar] = v2;
        }
        #pragma unroll
        for (int u = 0; u < 4; u++) {
            int kk = ac4 + u;
            int row = bn + ar, col = k0 + kk;
            float v1 = 0.0f, v2 = 0.0f;
            if (row < HH && col < HH) {
                v1 = Wz[row * HH2 + HH + col];
                v2 = Wh[row * HH2 + HH + col];
            }
            Bs1[kk][ar] = v1;
            Bs2[kk][ar] = v2;
        }
        __syncthreads();

        #pragma unroll
        for (int kk = 0; kk < BK; kk++) {
            float4 a1 = *reinterpret_cast<const float4*>(&As1[kk][ty * 4]);
            float4 a2 = *reinterpret_cast<const float4*>(&As2[kk][ty * 4]);
            float4 b1 = *reinterpret_cast<const float4*>(&Bs1[kk][tx * 4]);
            float4 b2 = *reinterpret_cast<const float4*>(&Bs2[kk][tx * 4]);
            float a1r[4] = {a1.x, a1.y, a1.z, a1.w};
            float a2r[4] = {a2.x, a2.y, a2.z, a2.w};
            float b1r[4] = {b1.x, b1.y, b1.z, b1.w};
            float b2r[4] = {b2.x, b2.y, b2.z, b2.w};
            #pragma unroll
            for (int i = 0; i < 4; i++)
                #pragma unroll
                for (int j = 0; j < 4; j++) {
                    acc1[i][j] = fmaf(a1r[i], b1r[j], acc1[i][j]);
                    acc2[i][j] = fmaf(a2r[i], b2r[j], acc2[i][j]);
                }
        }
        __syncthreads();
    }

    #pragma unroll
    for (int i = 0; i < 4; i++) {
        int row = bm + ty * 4 + i;
        if (row >= NM) continue;
        #pragma unroll
        for (int j = 0; j < 4; j++) {
            int col = bn + tx * 4 + j;
            if (col >= HH) continue;
            float z = sigmoid_(xz[row * HH + col] + acc1[i][j]);
            float p = tanh_   (xh[row * HH + col] + acc2[i][j]);
            float s = sumh[row * HH + col];
            float v = (1.0f - z) * s + z * p;
            if (row == 0) v = 0.0f;
            hout[row * HH + col] = v;
        }
    }
}

// ---------------- x = emb[fnode[fmess]] -------------------------------------
__global__ void x_gather(const float* __restrict__ emb,
                         const int* __restrict__ fnode,
                         const int* __restrict__ fmess,
                         float* __restrict__ x)
{
    int m = blockIdx.x;
    int j = blockIdx.y * blockDim.x + threadIdx.x;
    if (j >= HH) return;
    int e = fnode[fmess[m]];
    x[m * HH + j] = emb[e * HH + j];
}

// ---------------- first GRU step (h=0 specialization) -----------------------
__global__ void init_h(const float* __restrict__ xz, const float* __restrict__ xh,
                       float* __restrict__ h)
{
    int idx = blockIdx.x * blockDim.x + threadIdx.x;
    if (idx >= NM * HH) return;
    int m = idx / HH;
    float v = (m == 0) ? 0.0f : sigmoid_(xz[idx]) * tanh_(xh[idx]);
    h[idx] = v;
}

// ---------------- gather: sum_h and sum_gh (r fused) -------------------------
__global__ void gather_k(const float* __restrict__ h, const float* __restrict__ hU,
                         const float* __restrict__ xr, const int* __restrict__ mg,
                         float* __restrict__ sumh, float* __restrict__ sumgh)
{
    int m = blockIdx.x;
    int j = blockIdx.y * blockDim.x + threadIdx.x;
    if (j >= HH) return;
    float xrv = xr[m * HH + j];    // includes U_r bias
    float sh = 0.0f, sg = 0.0f;
    #pragma unroll
    for (int k = 0; k < KN; k++) {
        int idx = mg[m * KN + k];
        float hv = h [idx * HH + j];
        float hu = hU[idx * HH + j];
        float r = sigmoid_(xrv + hu);
        sh += hv;
        sg += r * hv;
    }
    sumh [m * HH + j] = sh;
    sumgh[m * HH + j] = sg;
}

// ---------------- root vectors: [emb(node) | sum_k h[node_graph]] -----------
__global__ void root_k(const float* __restrict__ emb, const int* __restrict__ fnode,
                       const int* __restrict__ ridx, const int* __restrict__ ng,
                       const float* __restrict__ h, float* __restrict__ root)
{
    int b = blockIdx.x;
    int node = ridx[b];
    int e = fnode[node];
    for (int j = threadIdx.x; j < HH; j += blockDim.x) {
        root[b * HH2 + j] = emb[e * HH + j];
        float s = 0.0f;
        #pragma unroll
        for (int k = 0; k < KN; k++) {
            int mi = ng[node * KN + k];
            s += h[mi * HH + j];
        }
        root[b * HH2 + HH + j] = s;
    }
}

// ---------------- final D3 dot product --------------------------------------
__global__ void d3_k(const float* __restrict__ d2, const float* __restrict__ w,
                     const float* __restrict__ bb, float* __restrict__ out)
{
    int b = blockIdx.x;
    float s = 0.0f;
    for (int i = threadIdx.x; i < HH; i += blockDim.x)
        s += d2[b * HH + i] * w[i];
    __shared__ float red[128];
    red[threadIdx.x] = s;
    __syncthreads();
    for (int st = 64; st > 0; st >>= 1) {
        if (threadIdx.x < st) red[threadIdx.x] += red[threadIdx.x + st];
        __syncthreads();
    }
    if (threadIdx.x == 0) out[b] = red[0] + bb[0];
}

// ---------------- launch ------------------------------------------------------
extern "C" void kernel_launch(void* const* d_in, const int* in_sizes, int n_in,
                              void* d_out, int out_size)
{
    const int*   fnode      = (const int*)d_in[0];
    const int*   fmess      = (const int*)d_in[1];
    const int*   node_graph = (const int*)d_in[2];
    const int*   mess_graph = (const int*)d_in[3];
    const int*   root_idx   = (const int*)d_in[4];
    const float* emb        = (const float*)d_in[5];
    const float* Wz         = (const float*)d_in[6];
    const float* Wz_b       = (const float*)d_in[7];
    const float* Wr         = (const float*)d_in[8];
    const float* Ur         = (const float*)d_in[9];
    const float* Ur_b       = (const float*)d_in[10];
    const float* Wh         = (const float*)d_in[11];
    const float* Wh_b       = (const float*)d_in[12];
    const float* D1w        = (const float*)d_in[13];
    const float* D1b        = (const float*)d_in[14];
    const float* D2w        = (const float*)d_in[15];
    const float* D2b        = (const float*)d_in[16];
    const float* D3w        = (const float*)d_in[17];
    const float* D3b        = (const float*)d_in[18];
    float* out = (float*)d_out;

    float *x, *xz, *xr, *xh, *hA, *hB, *hU, *sh, *sg, *root, *d1, *d2;
    cudaGetSymbolAddress((void**)&x,   g_x);
    cudaGetSymbolAddress((void**)&xz,  g_xz);
    cudaGetSymbolAddress((void**)&xr,  g_xr);
    cudaGetSymbolAddress((void**)&xh,  g_xh);
    cudaGetSymbolAddress((void**)&hA,  g_hA);
    cudaGetSymbolAddress((void**)&hB,  g_hB);
    cudaGetSymbolAddress((void**)&hU,  g_hU);
    cudaGetSymbolAddress((void**)&sh,  g_sh);
    cudaGetSymbolAddress((void**)&sg,  g_sg);
    cudaGetSymbolAddress((void**)&root, g_root);
    cudaGetSymbolAddress((void**)&d1,  g_d1);
    cudaGetSymbolAddress((void**)&d2,  g_d2);

    dim3 blk(256);
    dim3 gthr(NM, 2);                                   // per-message, per-j
    dim3 ggrid((HH + BN - 1) / BN, (NM + BM - 1) / BM); // 8 x 94

    // x = emb[fnode[fmess]]
    x_gather<<<gthr, blk>>>(emb, fnode, fmess, x);

    // Loop-invariant x-projections (biases folded in)
    gemm_nt<0><<<ggrid, blk>>>(x, HH, Wz, HH2, 0, Wz_b, xz, NM, HH, HH);
    gemm_nt<0><<<ggrid, blk>>>(x, HH, Wr, HH,  0, Ur_b, xr, NM, HH, HH);
    gemm_nt<0><<<ggrid, blk>>>(x, HH, Wh, HH2, 0, Wh_b, xh, NM, HH, HH);

    // Step 1 specialized for h0 = 0
    init_h<<<(NM * HH + 255) / 256, 256>>>(xz, xh, hA);

    float* hcur = hA;
    float* hnxt = hB;
    for (int it = 0; it < NDEPTH - 1; ++it) {
        // hU = h @ Ur^T  (pre-gather projection: 6x less GEMM work)
        gemm_nt<0><<<ggrid, blk>>>(hcur, HH, Ur, HH, 0, nullptr, hU, NM, HH, HH);
        // sum_h and sum_gh (r fused into the gather)
        gather_k<<<gthr, blk>>>(hcur, hU, xr, mess_graph, sh, sg);
        // fused dual-GEMM + GRU gate epilogue
        update_k<<<ggrid, blk>>>(sh, sg, Wz, Wh, xz, xh, hnxt);
        float* t = hcur; hcur = hnxt; hnxt = t;
    }

    // Root vectors and discriminator MLP
    root_k<<<NB, 256>>>(emb, fnode, root_idx, node_graph, hcur, root);

    dim3 dgrid((HH + BN - 1) / BN, (NB + BM - 1) / BM);
    gemm_nt<1><<<dgrid, blk>>>(root, HH2, D1w, HH2, 0, D1b, d1, NB, HH, HH2);
    gemm_nt<1><<<dgrid, blk>>>(d1,  HH,  D2w, HH,  0, D2b, d2, NB, HH, HH);
    d3_k<<<NB, 128>>>(d2, D3w, D3b, out);
}

// round 2
// speedup vs baseline: 1.6701x; 1.6701x over previous
#include <cuda_runtime.h>
#include <stdint.h>

// Problem constants
#define HH     450
#define HH2    900
#define NM     6000
#define NNODE  4000
#define KN     6
#define NB     256
#define NDEPTH 15

// ---------------- scratch (device globals) -----------------------------------
__device__ float g_x  [NM * HH];
__device__ float g_xz [NM * HH];
__device__ float g_xr [NM * HH];
__device__ float g_xh [NM * HH];
__device__ float g_hA [NM * HH];
__device__ float g_hB [NM * HH];
__device__ float g_hU [NM * HH];
__device__ float g_sh [NM * HH];
__device__ float g_sg [NM * HH];
__device__ float g_zp [NM * HH];
__device__ float g_root[NB * HH2];
__device__ float g_d1 [NB * HH];
__device__ float g_d2 [NB * HH];

// ---------------- math helpers ------------------------------------------------
__device__ __forceinline__ float sigmoid_(float t) {
    return 1.0f / (1.0f + __expf(-t));
}
__device__ __forceinline__ float tanh_(float t) {
    t = fminf(fmaxf(t, -12.0f), 12.0f);
    float e = __expf(2.0f * t);
    return (e - 1.0f) / (e + 1.0f);
}
__device__ __forceinline__ uint32_t f2tf32(float f) {
    uint32_t r;
    asm("cvt.rna.tf32.f32 %0, %1;" : "=r"(r) : "f"(f));
    return r;
}
__device__ __forceinline__ void mma8(float* c, const uint32_t* a, const uint32_t* b) {
    asm volatile(
        "mma.sync.aligned.m16n8k8.row.col.f32.tf32.tf32.f32 "
        "{%0,%1,%2,%3}, {%4,%5,%6,%7}, {%8,%9}, {%0,%1,%2,%3};"
        : "+f"(c[0]), "+f"(c[1]), "+f"(c[2]), "+f"(c[3])
        : "r"(a[0]), "r"(a[1]), "r"(a[2]), "r"(a[3]), "r"(b[0]), "r"(b[1]));
}

// ---------------- TF32 tensor-core GEMM ---------------------------------------
// C[Mv,Nv] = A[Mv,Kv](lda) @ Bw[Nv,Kv](ldb, +boff)^T
// EPI: 0 = +bias, 1 = +bias then leaky_relu(0.1), 2 = GRU gate epilogue
#define TBM 128
#define TBN 64
#define TBK 16
#define TSK 20   // padded smem k-stride (conflict-free: r*20 mod 32 distinct groups)

template <int EPI>
__global__ __launch_bounds__(256)
void gemm_tf32(const float* __restrict__ A, int lda,
               const float* __restrict__ Bw, int ldb, int boff,
               const float* __restrict__ bias,
               float* __restrict__ C,
               int Mv, int Nv, int Kv,
               // EPI==2 extras:
               const float* __restrict__ xz, const float* __restrict__ xh,
               const float* __restrict__ sumh, const float* __restrict__ zpre)
{
    __shared__ __align__(16) uint32_t As[TBM * TSK];
    __shared__ __align__(16) uint32_t Bs[TBN * TSK];

    const int bm   = blockIdx.y * TBM;
    const int bn   = blockIdx.x * TBN;
    const int tid  = threadIdx.x;
    const int lane = tid & 31;
    const int w    = tid >> 5;
    const int wm   = (w & 3) * 32;   // warp m offset within tile
    const int wn   = (w >> 2) * 32;  // warp n offset within tile
    const int gr   = lane >> 2;      // 0..7
    const int gc   = lane & 3;       // 0..3

    float acc[2][4][4] = {};

    for (int k0 = 0; k0 < Kv; k0 += TBK) {
        // ---- load A tile: 128 x 16, float2 global -> tf32 smem
        #pragma unroll
        for (int u = 0; u < 4; u++) {
            int id = u * 256 + tid;
            int r  = id >> 3;
            int c2 = (id & 7) * 2;
            int grow = bm + r, gcol = k0 + c2;
            float2 v = make_float2(0.0f, 0.0f);
            if (grow < Mv && gcol < Kv)
                v = *reinterpret_cast<const float2*>(A + (size_t)grow * lda + gcol);
            uint2 t2;
            t2.x = f2tf32(v.x);
            t2.y = f2tf32(v.y);
            *reinterpret_cast<uint2*>(&As[r * TSK + c2]) = t2;
        }
        // ---- load B tile: 64 x 16
        #pragma unroll
        for (int u = 0; u < 2; u++) {
            int id = u * 256 + tid;
            int r  = id >> 3;
            int c2 = (id & 7) * 2;
            int grow = bn + r, gcol = k0 + c2;
            float2 v = make_float2(0.0f, 0.0f);
            if (grow < Nv && gcol < Kv)
                v = *reinterpret_cast<const float2*>(Bw + (size_t)grow * ldb + boff + gcol);
            uint2 t2;
            t2.x = f2tf32(v.x);
            t2.y = f2tf32(v.y);
            *reinterpret_cast<uint2*>(&Bs[r * TSK + c2]) = t2;
        }
        __syncthreads();

        #pragma unroll
        for (int ks = 0; ks < TBK; ks += 8) {
            uint32_t af[2][4], bf[4][2];
            #pragma unroll
            for (int i = 0; i < 2; i++) {
                int r = wm + i * 16 + gr;
                af[i][0] = As[r * TSK + ks + gc];
                af[i][1] = As[(r + 8) * TSK + ks + gc];
                af[i][2] = As[r * TSK + ks + gc + 4];
                af[i][3] = As[(r + 8) * TSK + ks + gc + 4];
            }
            #pragma unroll
            for (int j = 0; j < 4; j++) {
                int r = wn + j * 8 + gr;
                bf[j][0] = Bs[r * TSK + ks + gc];
                bf[j][1] = Bs[r * TSK + ks + gc + 4];
            }
            #pragma unroll
            for (int i = 0; i < 2; i++)
                #pragma unroll
                for (int j = 0; j < 4; j++)
                    mma8(acc[i][j], af[i], bf[j]);
        }
        __syncthreads();
    }

    // ---- epilogue
    #pragma unroll
    for (int i = 0; i < 2; i++) {
        #pragma unroll
        for (int j = 0; j < 4; j++) {
            #pragma unroll
            for (int half = 0; half < 2; half++) {   // c0/c1 vs c2/c3 (row, row+8)
                int row = bm + wm + i * 16 + gr + half * 8;
                if (row >= Mv) continue;
                #pragma unroll
                for (int cc = 0; cc < 2; cc++) {
                    int col = bn + wn + j * 8 + gc * 2 + cc;
                    if (col >= Nv) continue;
                    float v = acc[i][j][half * 2 + cc];
                    if (EPI == 0 || EPI == 1) {
                        if (bias) v += bias[col];
                        if (EPI == 1) v = (v > 0.0f) ? v : 0.1f * v;
                        C[(size_t)row * Nv + col] = v;
                    } else {  // GRU gate epilogue: v = sum_gh @ Wh2^T
                        size_t o = (size_t)row * HH + col;
                        float z = sigmoid_(xz[o] + zpre[o]);
                        float p = tanh_(xh[o] + v);
                        float s = sumh[o];
                        float hv = (1.0f - z) * s + z * p;
                        if (row == 0) hv = 0.0f;
                        C[o] = hv;
                    }
                }
            }
        }
    }
}

// ---------------- x = emb[fnode[fmess]] ---------------------------------------
__global__ void x_gather(const float* __restrict__ emb,
                         const int* __restrict__ fnode,
                         const int* __restrict__ fmess,
                         float* __restrict__ x)
{
    int m = blockIdx.x;
    int j = blockIdx.y * blockDim.x + threadIdx.x;
    if (j >= HH) return;
    int e = fnode[fmess[m]];
    x[m * HH + j] = emb[e * HH + j];
}

// ---------------- first GRU step (h0 = 0) --------------------------------------
__global__ void init_h(const float* __restrict__ xz, const float* __restrict__ xh,
                       float* __restrict__ h)
{
    int idx = blockIdx.x * blockDim.x + threadIdx.x;
    if (idx >= NM * HH) return;
    int m = idx / HH;
    float v = (m == 0) ? 0.0f : sigmoid_(xz[idx]) * tanh_(xh[idx]);
    h[idx] = v;
}

// ---------------- gather: sum_h and sum_gh (r fused) ---------------------------
__global__ void gather_k(const float* __restrict__ h, const float* __restrict__ hU,
                         const float* __restrict__ xr, const int* __restrict__ mg,
                         float* __restrict__ sumh, float* __restrict__ sumgh)
{
    int m = blockIdx.x;
    int j = blockIdx.y * blockDim.x + threadIdx.x;
    if (j >= HH) return;
    float xrv = xr[m * HH + j];
    float sh = 0.0f, sg = 0.0f;
    #pragma unroll
    for (int k = 0; k < KN; k++) {
        int idx = mg[m * KN + k];
        float hv = h [idx * HH + j];
        float hu = hU[idx * HH + j];
        float r = sigmoid_(xrv + hu);
        sh += hv;
        sg += r * hv;
    }
    sumh [m * HH + j] = sh;
    sumgh[m * HH + j] = sg;
}

// ---------------- root vectors -------------------------------------------------
__global__ void root_k(const float* __restrict__ emb, const int* __restrict__ fnode,
                       const int* __restrict__ ridx, const int* __restrict__ ng,
                       const float* __restrict__ h, float* __restrict__ root)
{
    int b = blockIdx.x;
    int node = ridx[b];
    int e = fnode[node];
    for (int j = threadIdx.x; j < HH; j += blockDim.x) {
        root[b * HH2 + j] = emb[e * HH + j];
        float s = 0.0f;
        #pragma unroll
        for (int k = 0; k < KN; k++) {
            int mi = ng[node * KN + k];
            s += h[mi * HH + j];
        }
        root[b * HH2 + HH + j] = s;
    }
}

// ---------------- final D3 dot product -----------------------------------------
__global__ void d3_k(const float* __restrict__ d2, const float* __restrict__ w,
                     const float* __restrict__ bb, float* __restrict__ out)
{
    int b = blockIdx.x;
    float s = 0.0f;
    for (int i = threadIdx.x; i < HH; i += blockDim.x)
        s += d2[b * HH + i] * w[i];
    __shared__ float red[128];
    red[threadIdx.x] = s;
    __syncthreads();
    for (int st = 64; st > 0; st >>= 1) {
        if (threadIdx.x < st) red[threadIdx.x] += red[threadIdx.x + st];
        __syncthreads();
    }
    if (threadIdx.x == 0) out[b] = red[0] + bb[0];
}

// ---------------- launch ---------------------------------------------------------
extern "C" void kernel_launch(void* const* d_in, const int* in_sizes, int n_in,
                              void* d_out, int out_size)
{
    const int*   fnode      = (const int*)d_in[0];
    const int*   fmess      = (const int*)d_in[1];
    const int*   node_graph = (const int*)d_in[2];
    const int*   mess_graph = (const int*)d_in[3];
    const int*   root_idx   = (const int*)d_in[4];
    const float* emb        = (const float*)d_in[5];
    const float* Wz         = (const float*)d_in[6];
    const float* Wz_b       = (const float*)d_in[7];
    const float* Wr         = (const float*)d_in[8];
    const float* Ur         = (const float*)d_in[9];
    const float* Ur_b       = (const float*)d_in[10];
    const float* Wh         = (const float*)d_in[11];
    const float* Wh_b       = (const float*)d_in[12];
    const float* D1w        = (const float*)d_in[13];
    const float* D1b        = (const float*)d_in[14];
    const float* D2w        = (const float*)d_in[15];
    const float* D2b        = (const float*)d_in[16];
    const float* D3w        = (const float*)d_in[17];
    const float* D3b        = (const float*)d_in[18];
    float* out = (float*)d_out;

    float *x, *xz, *xr, *xh, *hA, *hB, *hU, *sh, *sg, *zp, *root, *d1, *d2;
    cudaGetSymbolAddress((void**)&x,    g_x);
    cudaGetSymbolAddress((void**)&xz,   g_xz);
    cudaGetSymbolAddress((void**)&xr,   g_xr);
    cudaGetSymbolAddress((void**)&xh,   g_xh);
    cudaGetSymbolAddress((void**)&hA,   g_hA);
    cudaGetSymbolAddress((void**)&hB,   g_hB);
    cudaGetSymbolAddress((void**)&hU,   g_hU);
    cudaGetSymbolAddress((void**)&sh,   g_sh);
    cudaGetSymbolAddress((void**)&sg,   g_sg);
    cudaGetSymbolAddress((void**)&zp,   g_zp);
    cudaGetSymbolAddress((void**)&root, g_root);
    cudaGetSymbolAddress((void**)&d1,   g_d1);
    cudaGetSymbolAddress((void**)&d2,   g_d2);

    dim3 blk(256);
    dim3 gthr(NM, 2);
    dim3 ggrid((HH + TBN - 1) / TBN, (NM + TBM - 1) / TBM);   // 8 x 47

    // x = emb[fnode[fmess]]
    x_gather<<<gthr, blk>>>(emb, fnode, fmess, x);

    // Loop-invariant x-projections (biases folded in)
    gemm_tf32<0><<<ggrid, blk>>>(x, HH, Wz, HH2, 0, Wz_b, xz, NM, HH, HH,
                                 nullptr, nullptr, nullptr, nullptr);
    gemm_tf32<0><<<ggrid, blk>>>(x, HH, Wr, HH,  0, Ur_b, xr, NM, HH, HH,
                                 nullptr, nullptr, nullptr, nullptr);
    gemm_tf32<0><<<ggrid, blk>>>(x, HH, Wh, HH2, 0, Wh_b, xh, NM, HH, HH,
                                 nullptr, nullptr, nullptr, nullptr);

    // Step 1 specialized for h0 = 0
    init_h<<<(NM * HH + 255) / 256, 256>>>(xz, xh, hA);

    float* hcur = hA;
    float* hnxt = hB;
    for (int it = 0; it < NDEPTH - 1; ++it) {
        // hU = h @ Ur^T (pre-gather projection)
        gemm_tf32<0><<<ggrid, blk>>>(hcur, HH, Ur, HH, 0, nullptr, hU, NM, HH, HH,
                                     nullptr, nullptr, nullptr, nullptr);
        // sum_h, sum_gh (r fused into the gather)
        gather_k<<<gthr, blk>>>(hcur, hU, xr, mess_graph, sh, sg);
        // zpre = sum_h @ Wz2^T
        gemm_tf32<0><<<ggrid, blk>>>(sh, HH, Wz, HH2, HH, nullptr, zp, NM, HH, HH,
                                     nullptr, nullptr, nullptr, nullptr);
        // h_new = GRU(acc = sum_gh @ Wh2^T) fused epilogue
        gemm_tf32<2><<<ggrid, blk>>>(sg, HH, Wh, HH2, HH, nullptr, hnxt, NM, HH, HH,
                                     xz, xh, sh, zp);
        float* t = hcur; hcur = hnxt; hnxt = t;
    }

    // Root vectors and discriminator MLP
    root_k<<<NB, 256>>>(emb, fnode, root_idx, node_graph, hcur, root);

    dim3 dgrid((HH + TBN - 1) / TBN, (NB + TBM - 1) / TBM);   // 8 x 2
    gemm_tf32<1><<<dgrid, blk>>>(root, HH2, D1w, HH2, 0, D1b, d1, NB, HH, HH2,
                                 nullptr, nullptr, nullptr, nullptr);
    gemm_tf32<1><<<dgrid, blk>>>(d1,  HH,  D2w, HH,  0, D2b, d2, NB, HH, HH,
                                 nullptr, nullptr, nullptr, nullptr);
    d3_k<<<NB, 128>>>(d2, D3w, D3b, out);
}

// round 3
// speedup vs baseline: 2.5096x; 1.5026x over previous
#include <cuda_runtime.h>
#include <stdint.h>

// Problem constants
#define HH     450
#define HH2    900
#define NM     6000
#define KN     6
#define NB     256
#define NDEPTH 15

#define SP   464           // padded row stride (29*16)
#define SP2  928           // padded 2H stride (58*16)
#define MPAD 6016          // padded message rows (47*128)
#define WPAD 512           // padded weight rows

// ---------------- scratch (device globals) -----------------------------------
__device__ __align__(16) float g_x  [MPAD * SP];
__device__ __align__(16) float g_xz [MPAD * SP];
__device__ __align__(16) float g_xr [MPAD * SP];
__device__ __align__(16) float g_xh [MPAD * SP];
__device__ __align__(16) float g_hA [MPAD * SP];
__device__ __align__(16) float g_hB [MPAD * SP];
__device__ __align__(16) float g_hU [MPAD * SP];
__device__ __align__(16) float g_sh [MPAD * SP];
__device__ __align__(16) float g_sg [MPAD * SP];
__device__ __align__(16) float g_zp [MPAD * SP];
__device__ __align__(16) float g_root[NB * SP2];
__device__ __align__(16) float g_d1 [NB * SP];
__device__ __align__(16) float g_d2 [NB * SP];
// pre-rounded, repacked weights
__device__ __align__(16) float g_wz1[WPAD * SP];
__device__ __align__(16) float g_wz2[WPAD * SP];
__device__ __align__(16) float g_wr [WPAD * SP];
__device__ __align__(16) float g_ur [WPAD * SP];
__device__ __align__(16) float g_wh1[WPAD * SP];
__device__ __align__(16) float g_wh2[WPAD * SP];
__device__ __align__(16) float g_d1w[WPAD * SP2];
__device__ __align__(16) float g_d2w[WPAD * SP];

// ---------------- math helpers ------------------------------------------------
__device__ __forceinline__ float sigmoid_(float t) {
    return 1.0f / (1.0f + __expf(-t));
}
__device__ __forceinline__ float tanh_(float t) {
    t = fminf(fmaxf(t, -12.0f), 12.0f);
    float e = __expf(2.0f * t);
    return (e - 1.0f) / (e + 1.0f);
}
__device__ __forceinline__ uint32_t f2tf32(float f) {
    uint32_t r;
    asm("cvt.rna.tf32.f32 %0, %1;" : "=r"(r) : "f"(f));
    return r;
}
__device__ __forceinline__ float tf32r(float f) {
    return __uint_as_float(f2tf32(f));
}
__device__ __forceinline__ uint32_t smem_u32(const void* p) {
    uint32_t a;
    asm("{ .reg .u64 t; cvta.to.shared.u64 t, %1; cvt.u32.u64 %0, t; }"
        : "=r"(a) : "l"(p));
    return a;
}
__device__ __forceinline__ void cpa16(uint32_t dst, const void* src) {
    asm volatile("cp.async.cg.shared.global [%0], [%1], 16;\n" :: "r"(dst), "l"(src));
}
__device__ __forceinline__ void mma8(float* c, const uint32_t* a, const uint32_t* b) {
    asm volatile(
        "mma.sync.aligned.m16n8k8.row.col.f32.tf32.tf32.f32 "
        "{%0,%1,%2,%3}, {%4,%5,%6,%7}, {%8,%9}, {%0,%1,%2,%3};"
        : "+f"(c[0]), "+f"(c[1]), "+f"(c[2]), "+f"(c[3])
        : "r"(a[0]), "r"(a[1]), "r"(a[2]), "r"(a[3]), "r"(b[0]), "r"(b[1]));
}

// ---------------- pipelined TF32 GEMM -----------------------------------------
// C[.,Nv450] = A[M x K](lda) @ Bw[450 x K packed WPAD rows](ldb)^T
// Buffers are zero-padded: NO bounds checks in the main loop.
// EPI: 0 = (+bias), 1 = (+bias, leaky 0.1), 2 = GRU gate epilogue
#define TBM 128
#define TBN 64
#define TBK 16
#define TSK 20

#define LOAD_STAGE(kc_, s_)                                                     \
    do {                                                                        \
        int k0_ = (kc_) * TBK;                                                  \
        const float* Ab_ = A + (size_t)bm * lda + k0_;                          \
        _Pragma("unroll")                                                       \
        for (int u_ = 0; u_ < 4; u_++) {                                        \
            int id_ = u_ * 128 + tid;                                           \
            int r_ = id_ >> 2, cq_ = (id_ & 3) * 4;                             \
            cpa16(sAu + (((s_) * TBM + r_) * TSK + cq_) * 4,                    \
                  Ab_ + (size_t)r_ * lda + cq_);                                \
        }                                                                       \
        const float* Bb_ = Bw + (size_t)bn * ldb + k0_;                         \
        _Pragma("unroll")                                                       \
        for (int u_ = 0; u_ < 2; u_++) {                                        \
            int id_ = u_ * 128 + tid;                                           \
            int r_ = id_ >> 2, cq_ = (id_ & 3) * 4;                             \
            cpa16(sBu + (((s_) * TBN + r_) * TSK + cq_) * 4,                    \
                  Bb_ + (size_t)r_ * ldb + cq_);                                \
        }                                                                       \
    } while (0)

template <int EPI>
__global__ __launch_bounds__(128)
void gemm_p(const float* __restrict__ A, int lda,
            const float* __restrict__ Bw, int ldb,
            const float* __restrict__ bias,
            float* __restrict__ C, int ldc, int Kc,
            const float* __restrict__ xz, const float* __restrict__ xh,
            const float* __restrict__ sumh, const float* __restrict__ zpre)
{
    __shared__ __align__(16) float As[2 * TBM * TSK];
    __shared__ __align__(16) float Bs[2 * TBN * TSK];

    const int bm = blockIdx.y * TBM;
    const int bn = blockIdx.x * TBN;
    const int tid  = threadIdx.x;
    const int lane = tid & 31;
    const int w    = tid >> 5;
    const int wm = (w & 1) * 64;
    const int wn = (w >> 1) * 32;
    const int gr = lane >> 2;
    const int gc = lane & 3;

    const uint32_t sAu = smem_u32(As);
    const uint32_t sBu = smem_u32(Bs);

    float acc[4][4][4] = {};

    LOAD_STAGE(0, 0);
    asm volatile("cp.async.commit_group;\n");

    for (int kc = 0; kc < Kc; kc++) {
        int s = kc & 1;
        if (kc + 1 < Kc) LOAD_STAGE(kc + 1, (kc + 1) & 1);
        asm volatile("cp.async.commit_group;\n");
        asm volatile("cp.async.wait_group 1;\n");
        __syncthreads();

        const float* Asb = As + s * TBM * TSK;
        const float* Bsb = Bs + s * TBN * TSK;

        #pragma unroll
        for (int ks = 0; ks < TBK; ks += 8) {
            uint32_t af[4][4], bf[4][2];
            #pragma unroll
            for (int mt = 0; mt < 4; mt++) {
                int r = wm + mt * 16 + gr;
                af[mt][0] = f2tf32(Asb[r * TSK + ks + gc]);
                af[mt][1] = f2tf32(Asb[(r + 8) * TSK + ks + gc]);
                af[mt][2] = f2tf32(Asb[r * TSK + ks + gc + 4]);
                af[mt][3] = f2tf32(Asb[(r + 8) * TSK + ks + gc + 4]);
            }
            #pragma unroll
            for (int nt = 0; nt < 4; nt++) {
                int r = wn + nt * 8 + gr;
                bf[nt][0] = __float_as_uint(Bsb[r * TSK + ks + gc]);      // pre-rounded
                bf[nt][1] = __float_as_uint(Bsb[r * TSK + ks + gc + 4]);
            }
            #pragma unroll
            for (int mt = 0; mt < 4; mt++)
                #pragma unroll
                for (int nt = 0; nt < 4; nt++)
                    mma8(acc[mt][nt], af[mt], bf[nt]);
        }
        __syncthreads();
    }

    // ---- epilogue (float2 stores; cols pairs never straddle 450)
    #pragma unroll
    for (int mt = 0; mt < 4; mt++) {
        #pragma unroll
        for (int half = 0; half < 2; half++) {
            int row = bm + wm + mt * 16 + gr + half * 8;
            #pragma unroll
            for (int nt = 0; nt < 4; nt++) {
                int col = bn + wn + nt * 8 + gc * 2;
                if (col >= SP) continue;   // tile overhang beyond padded width
                float v0 = acc[mt][nt][half * 2 + 0];
                float v1 = acc[mt][nt][half * 2 + 1];
                float2 o2;
                if (col < HH) {
                    if (EPI == 0) {
                        if (bias) { v0 += bias[col]; v1 += bias[col + 1]; }
                        o2 = make_float2(v0, v1);
                    } else if (EPI == 1) {
                        v0 += bias[col]; v1 += bias[col + 1];
                        o2.x = (v0 > 0.0f) ? v0 : 0.1f * v0;
                        o2.y = (v1 > 0.0f) ? v1 : 0.1f * v1;
                    } else {
                        size_t o = (size_t)row * SP + col;
                        float2 xzv = *reinterpret_cast<const float2*>(xz + o);
                        float2 xhv = *reinterpret_cast<const float2*>(xh + o);
                        float2 shv = *reinterpret_cast<const float2*>(sumh + o);
                        float2 zpv = *reinterpret_cast<const float2*>(zpre + o);
                        float z0 = sigmoid_(xzv.x + zpv.x);
                        float z1 = sigmoid_(xzv.y + zpv.y);
                        float p0 = tanh_(xhv.x + v0);
                        float p1 = tanh_(xhv.y + v1);
                        o2.x = (1.0f - z0) * shv.x + z0 * p0;
                        o2.y = (1.0f - z1) * shv.y + z1 * p1;
                        if (row == 0) { o2.x = 0.0f; o2.y = 0.0f; }
                    }
                } else {
                    o2 = make_float2(0.0f, 0.0f);   // keep pads zero
                }
                *reinterpret_cast<float2*>(C + (size_t)row * ldc + col) = o2;
            }
        }
    }
}

// ---------------- weight prep: round to tf32, repack zero-padded ---------------
__global__ void prep_w(const float* __restrict__ Wz, const float* __restrict__ Wr,
                       const float* __restrict__ Ur, const float* __restrict__ Wh,
                       const float* __restrict__ D1, const float* __restrict__ D2,
                       float* __restrict__ wz1, float* __restrict__ wz2,
                       float* __restrict__ wr,  float* __restrict__ ur,
                       float* __restrict__ wh1, float* __restrict__ wh2,
                       float* __restrict__ d1w, float* __restrict__ d2w)
{
    int mat = blockIdx.y;
    int idx = blockIdx.x * 256 + threadIdx.x;
    if (mat < 7) {
        if (idx >= WPAD * SP) return;
        int r = idx / SP, c = idx % SP;
        float v = 0.0f;
        if (r < HH && c < HH) {
            switch (mat) {
                case 0: v = Wz[r * HH2 + c];      break;
                case 1: v = Wz[r * HH2 + HH + c]; break;
                case 2: v = Wr[r * HH + c];       break;
                case 3: v = Ur[r * HH + c];       break;
                case 4: v = Wh[r * HH2 + c];      break;
                case 5: v = Wh[r * HH2 + HH + c]; break;
                case 6: v = D2[r * HH + c];       break;
            }
            v = tf32r(v);
        }
        switch (mat) {
            case 0: wz1[idx] = v; break;
            case 1: wz2[idx] = v; break;
            case 2: wr [idx] = v; break;
            case 3: ur [idx] = v; break;
            case 4: wh1[idx] = v; break;
            case 5: wh2[idx] = v; break;
            case 6: d2w[idx] = v; break;
        }
    } else {
        if (idx >= WPAD * SP2) return;
        int r = idx / SP2, c = idx % SP2;
        float v = 0.0f;
        if (r < HH) {
            if (c < HH)                    v = D1[r * HH2 + c];
            else if (c >= SP && c - SP < HH) v = D1[r * HH2 + HH + (c - SP)];
            v = tf32r(v);
        }
        d1w[idx] = v;
    }
}

// ---------------- x = emb[fnode[fmess]], zero-padded ---------------------------
__global__ void x_gather(const float* __restrict__ emb,
                         const int* __restrict__ fnode,
                         const int* __restrict__ fmess,
                         float* __restrict__ x)
{
    int m = blockIdx.x;
    int j = threadIdx.x * 2;
    if (j >= SP) return;
    float2 v = make_float2(0.0f, 0.0f);
    if (m < NM && j < HH) {
        int e = fnode[fmess[m]];
        v = *reinterpret_cast<const float2*>(emb + (size_t)e * HH + j);
    }
    *reinterpret_cast<float2*>(x + (size_t)m * SP + j) = v;
}

// ---------------- first GRU step (h0 = 0) --------------------------------------
__global__ void init_h(const float* __restrict__ xz, const float* __restrict__ xh,
                       float* __restrict__ h)
{
    int m = blockIdx.x;
    int j = threadIdx.x * 2;
    if (j >= SP) return;
    size_t o = (size_t)m * SP + j;
    float2 v = make_float2(0.0f, 0.0f);
    if (m > 0 && m < NM && j < HH) {
        float2 a = *reinterpret_cast<const float2*>(xz + o);
        float2 b = *reinterpret_cast<const float2*>(xh + o);
        v.x = sigmoid_(a.x) * tanh_(b.x);
        v.y = sigmoid_(a.y) * tanh_(b.y);
    }
    *reinterpret_cast<float2*>(h + o) = v;
}

// ---------------- gather: sum_h, sum_gh (r fused), float4 ----------------------
__global__ void gather_k(const float* __restrict__ h, const float* __restrict__ hU,
                         const float* __restrict__ xr, const int* __restrict__ mg,
                         float* __restrict__ sumh, float* __restrict__ sumgh)
{
    int m = blockIdx.x;
    int j = threadIdx.x * 4;
    if (j >= SP) return;
    size_t o = (size_t)m * SP + j;
    float4 xr4 = *reinterpret_cast<const float4*>(xr + o);
    float4 sh4 = make_float4(0.f, 0.f, 0.f, 0.f);
    float4 sg4 = make_float4(0.f, 0.f, 0.f, 0.f);
    #pragma unroll
    for (int k = 0; k < KN; k++) {
        int idx = mg[m * KN + k];
        size_t q = (size_t)idx * SP + j;
        float4 h4  = *reinterpret_cast<const float4*>(h  + q);
        float4 hu4 = *reinterpret_cast<const float4*>(hU + q);
        sh4.x += h4.x; sh4.y += h4.y; sh4.z += h4.z; sh4.w += h4.w;
        sg4.x += sigmoid_(xr4.x + hu4.x) * h4.x;
        sg4.y += sigmoid_(xr4.y + hu4.y) * h4.y;
        sg4.z += sigmoid_(xr4.z + hu4.z) * h4.z;
        sg4.w += sigmoid_(xr4.w + hu4.w) * h4.w;
    }
    *reinterpret_cast<float4*>(sumh  + o) = sh4;
    *reinterpret_cast<float4*>(sumgh + o) = sg4;
}

// ---------------- root vectors: [emb | pad | sum | pad], stride 928 ------------
__global__ void root_k(const float* __restrict__ emb, const int* __restrict__ fnode,
                       const int* __restrict__ ridx, const int* __restrict__ ng,
                       const float* __restrict__ h, float* __restrict__ root)
{
    int b = blockIdx.x;
    int node = ridx[b];
    int e = fnode[node];
    for (int j = threadIdx.x; j < SP2; j += blockDim.x) {
        float v = 0.0f;
        if (j < HH) {
            v = emb[(size_t)e * HH + j];
        } else if (j >= SP && j - SP < HH) {
            int c = j - SP;
            float s = 0.0f;
            #pragma unroll
            for (int k = 0; k < KN; k++) {
                int mi = ng[node * KN + k];
                s += h[(size_t)mi * SP + c];
            }
            v = s;
        }
        root[(size_t)b * SP2 + j] = v;
    }
}

// ---------------- final D3 dot product -----------------------------------------
__global__ void d3_k(const float* __restrict__ d2, const float* __restrict__ w,
                     const float* __restrict__ bb, float* __restrict__ out)
{
    int b = blockIdx.x;
    float s = 0.0f;
    for (int i = threadIdx.x; i < HH; i += blockDim.x)
        s += d2[(size_t)b * SP + i] * w[i];
    __shared__ float red[128];
    red[threadIdx.x] = s;
    __syncthreads();
    for (int st = 64; st > 0; st >>= 1) {
        if (threadIdx.x < st) red[threadIdx.x] += red[threadIdx.x + st];
        __syncthreads();
    }
    if (threadIdx.x == 0) out[b] = red[0] + bb[0];
}

// ---------------- launch ---------------------------------------------------------
extern "C" void kernel_launch(void* const* d_in, const int* in_sizes, int n_in,
                              void* d_out, int out_size)
{
    const int*   fnode      = (const int*)d_in[0];
    const int*   fmess      = (const int*)d_in[1];
    const int*   node_graph = (const int*)d_in[2];
    const int*   mess_graph = (const int*)d_in[3];
    const int*   root_idx   = (const int*)d_in[4];
    const float* emb        = (const float*)d_in[5];
    const float* Wz         = (const float*)d_in[6];
    const float* Wz_b       = (const float*)d_in[7];
    const float* Wr         = (const float*)d_in[8];
    const float* Ur         = (const float*)d_in[9];
    const float* Ur_b       = (const float*)d_in[10];
    const float* Wh         = (const float*)d_in[11];
    const float* Wh_b       = (const float*)d_in[12];
    const float* D1w        = (const float*)d_in[13];
    const float* D1b        = (const float*)d_in[14];
    const float* D2w        = (const float*)d_in[15];
    const float* D2b        = (const float*)d_in[16];
    const float* D3w        = (const float*)d_in[17];
    const float* D3b        = (const float*)d_in[18];
    float* out = (float*)d_out;

    float *x, *xz, *xr, *xh, *hA, *hB, *hU, *sh, *sg, *zp, *root, *d1, *d2;
    float *wz1, *wz2, *wr, *ur, *wh1, *wh2, *d1w, *d2w;
    cudaGetSymbolAddress((void**)&x,    g_x);
    cudaGetSymbolAddress((void**)&xz,   g_xz);
    cudaGetSymbolAddress((void**)&xr,   g_xr);
    cudaGetSymbolAddress((void**)&xh,   g_xh);
    cudaGetSymbolAddress((void**)&hA,   g_hA);
    cudaGetSymbolAddress((void**)&hB,   g_hB);
    cudaGetSymbolAddress((void**)&hU,   g_hU);
    cudaGetSymbolAddress((void**)&sh,   g_sh);
    cudaGetSymbolAddress((void**)&sg,   g_sg);
    cudaGetSymbolAddress((void**)&zp,   g_zp);
    cudaGetSymbolAddress((void**)&root, g_root);
    cudaGetSymbolAddress((void**)&d1,   g_d1);
    cudaGetSymbolAddress((void**)&d2,   g_d2);
    cudaGetSymbolAddress((void**)&wz1,  g_wz1);
    cudaGetSymbolAddress((void**)&wz2,  g_wz2);
    cudaGetSymbolAddress((void**)&wr,   g_wr);
    cudaGetSymbolAddress((void**)&ur,   g_ur);
    cudaGetSymbolAddress((void**)&wh1,  g_wh1);
    cudaGetSymbolAddress((void**)&wh2,  g_wh2);
    cudaGetSymbolAddress((void**)&d1w,  g_d1w);
    cudaGetSymbolAddress((void**)&d2w,  g_d2w);

    const int KC1 = SP / TBK;    // 29
    const int KC2 = SP2 / TBK;   // 58

    // weight prep (round + repack, zero-padded)
    dim3 pgrid((WPAD * SP2 + 255) / 256, 8);
    prep_w<<<pgrid, 256>>>(Wz, Wr, Ur, Wh, D1w, D2w,
                           wz1, wz2, wr, ur, wh1, wh2, d1w, d2w);

    // x = emb[fnode[fmess]]
    x_gather<<<MPAD, SP / 2>>>(emb, fnode, fmess, x);

    dim3 ggrid(SP / TBN + (SP % TBN ? 1 : 0), MPAD / TBM);   // 8 x 47 (SP=464 -> 8)
    dim3 blk(128);

    // Loop-invariant x-projections
    gemm_p<0><<<ggrid, blk>>>(x, SP, wz1, SP, Wz_b, xz, SP, KC1, 0, 0, 0, 0);
    gemm_p<0><<<ggrid, blk>>>(x, SP, wr,  SP, Ur_b, xr, SP, KC1, 0, 0, 0, 0);
    gemm_p<0><<<ggrid, blk>>>(x, SP, wh1, SP, Wh_b, xh, SP, KC1, 0, 0, 0, 0);

    // Step 1 specialized for h0 = 0
    init_h<<<MPAD, SP / 2>>>(xz, xh, hA);

    float* hcur = hA;
    float* hnxt = hB;
    for (int it = 0; it < NDEPTH - 1; ++it) {
        gemm_p<0><<<ggrid, blk>>>(hcur, SP, ur, SP, nullptr, hU, SP, KC1, 0, 0, 0, 0);
        gather_k<<<NM, SP / 4>>>(hcur, hU, xr, mess_graph, sh, sg);
        gemm_p<0><<<ggrid, blk>>>(sh, SP, wz2, SP, nullptr, zp, SP, KC1, 0, 0, 0, 0);
        gemm_p<2><<<ggrid, blk>>>(sg, SP, wh2, SP, nullptr, hnxt, SP, KC1,
                                  xz, xh, sh, zp);
        float* t = hcur; hcur = hnxt; hnxt = t;
    }

    // Root vectors + discriminator MLP
    root_k<<<NB, 256>>>(emb, fnode, root_idx, node_graph, hcur, root);

    dim3 dgrid(8, NB / TBM);   // 8 x 2
    gemm_p<1><<<dgrid, blk>>>(root, SP2, d1w, SP2, D1b, d1, SP, KC2, 0, 0, 0, 0);
    gemm_p<1><<<dgrid, blk>>>(d1,   SP,  d2w, SP,  D2b, d2, SP, KC1, 0, 0, 0, 0);
    d3_k<<<NB, 128>>>(d2, D3w, D3b, out);
}

// round 4
// speedup vs baseline: 2.5929x; 1.0332x over previous
#include <cuda_runtime.h>
#include <stdint.h>

// Problem constants
#define HH     450
#define HH2    900
#define NM     6000
#define KN     6
#define NB     256
#define NDEPTH 15

#define SP   464           // padded row stride (29*16)
#define SP2  928           // padded 2H stride (58*16)
#define MPAD 6016          // padded message rows (47*128)
#define WPAD 512           // padded weight rows

// ---------------- scratch (device globals) -----------------------------------
__device__ __align__(16) float g_x  [MPAD * SP];
__device__ __align__(16) float g_xz [MPAD * SP];
__device__ __align__(16) float g_xr [MPAD * SP];
__device__ __align__(16) float g_xh [MPAD * SP];
__device__ __align__(16) float g_hA [MPAD * SP];
__device__ __align__(16) float g_hB [MPAD * SP];
__device__ __align__(16) float g_hU [MPAD * SP];
__device__ __align__(16) float g_sh [MPAD * SP];
__device__ __align__(16) float g_sg [MPAD * SP];
__device__ __align__(16) float g_root[NB * SP2];
__device__ __align__(16) float g_d1 [NB * SP];
__device__ __align__(16) float g_d2 [NB * SP];
// pre-rounded, repacked weights
__device__ __align__(16) float g_wz1[WPAD * SP];
__device__ __align__(16) float g_wz2[WPAD * SP];
__device__ __align__(16) float g_wr [WPAD * SP];
__device__ __align__(16) float g_ur [WPAD * SP];
__device__ __align__(16) float g_wh1[WPAD * SP];
__device__ __align__(16) float g_wh2[WPAD * SP];
__device__ __align__(16) float g_d1w[WPAD * SP2];
__device__ __align__(16) float g_d2w[WPAD * SP];

// ---------------- math helpers ------------------------------------------------
__device__ __forceinline__ float sigmoid_(float t) {
    return 1.0f / (1.0f + __expf(-t));
}
__device__ __forceinline__ float tanh_(float t) {
    t = fminf(fmaxf(t, -12.0f), 12.0f);
    float e = __expf(2.0f * t);
    return (e - 1.0f) / (e + 1.0f);
}
__device__ __forceinline__ uint32_t f2tf32(float f) {
    uint32_t r;
    asm("cvt.rna.tf32.f32 %0, %1;" : "=r"(r) : "f"(f));
    return r;
}
__device__ __forceinline__ float tf32r(float f) {
    return __uint_as_float(f2tf32(f));
}
__device__ __forceinline__ uint32_t smem_u32(const void* p) {
    uint32_t a;
    asm("{ .reg .u64 t; cvta.to.shared.u64 t, %1; cvt.u32.u64 %0, t; }"
        : "=r"(a) : "l"(p));
    return a;
}
__device__ __forceinline__ void cpa16(uint32_t dst, const void* src) {
    asm volatile("cp.async.cg.shared.global [%0], [%1], 16;\n" :: "r"(dst), "l"(src));
}
__device__ __forceinline__ void mma8(float* c, const uint32_t* a, const uint32_t* b) {
    asm volatile(
        "mma.sync.aligned.m16n8k8.row.col.f32.tf32.tf32.f32 "
        "{%0,%1,%2,%3}, {%4,%5,%6,%7}, {%8,%9}, {%0,%1,%2,%3};"
        : "+f"(c[0]), "+f"(c[1]), "+f"(c[2]), "+f"(c[3])
        : "r"(a[0]), "r"(a[1]), "r"(a[2]), "r"(a[3]), "r"(b[0]), "r"(b[1]));
}

#define TBM 128
#define TBN 64
#define TBK 16
#define TSK 20
#define ASTG (TBM * TSK)   // 2560 floats per A stage
#define BSTG (TBN * TSK)   // 1280 floats per B stage

// issue A-tile (128x16) + B-tile (64x16) async copies for chunk kc into stage s
#define LOAD_AB(Aptr_, Alda_, Bptr_, Bldb_, kc_, dA_, dB_)                      \
    do {                                                                        \
        int k0_ = (kc_) * TBK;                                                  \
        const float* Ab_ = (Aptr_) + (size_t)bm * (Alda_) + k0_;                \
        _Pragma("unroll")                                                       \
        for (int u_ = 0; u_ < 2; u_++) {                                        \
            int id_ = u_ * 256 + tid;                                           \
            int r_ = id_ >> 2, cq_ = (id_ & 3) * 4;                             \
            cpa16((dA_) + (r_ * TSK + cq_) * 4,                                 \
                  Ab_ + (size_t)r_ * (Alda_) + cq_);                            \
        }                                                                       \
        {                                                                       \
            int r_ = tid >> 2, cq_ = (tid & 3) * 4;                             \
            cpa16((dB_) + (r_ * TSK + cq_) * 4,                                 \
                  (Bptr_) + (size_t)(bn + r_) * (Bldb_) + k0_ + cq_);           \
        }                                                                       \
    } while (0)

// compute one TBK chunk: af converted from fp32, bf pre-rounded
#define COMPUTE_CHUNK(Asb_, Bsb_, accv_)                                        \
    do {                                                                        \
        _Pragma("unroll")                                                       \
        for (int ks_ = 0; ks_ < TBK; ks_ += 8) {                                \
            uint32_t af_[2][4], bf_[4][2];                                      \
            _Pragma("unroll")                                                   \
            for (int mt_ = 0; mt_ < 2; mt_++) {                                 \
                int r_ = wm + mt_ * 16 + gr;                                    \
                af_[mt_][0] = f2tf32((Asb_)[r_ * TSK + ks_ + gc]);              \
                af_[mt_][1] = f2tf32((Asb_)[(r_ + 8) * TSK + ks_ + gc]);        \
                af_[mt_][2] = f2tf32((Asb_)[r_ * TSK + ks_ + gc + 4]);          \
                af_[mt_][3] = f2tf32((Asb_)[(r_ + 8) * TSK + ks_ + gc + 4]);    \
            }                                                                   \
            _Pragma("unroll")                                                   \
            for (int nt_ = 0; nt_ < 4; nt_++) {                                 \
                int r_ = wn + nt_ * 8 + gr;                                     \
                bf_[nt_][0] = __float_as_uint((Bsb_)[r_ * TSK + ks_ + gc]);     \
                bf_[nt_][1] = __float_as_uint((Bsb_)[r_ * TSK + ks_ + gc + 4]); \
            }                                                                   \
            _Pragma("unroll")                                                   \
            for (int mt_ = 0; mt_ < 2; mt_++)                                   \
                _Pragma("unroll")                                               \
                for (int nt_ = 0; nt_ < 4; nt_++)                               \
                    mma8((accv_)[mt_][nt_], af_[mt_], bf_[nt_]);                \
        }                                                                       \
    } while (0)

// ---------------- single GEMM, 3-stage pipeline --------------------------------
// C[., 450(+pad)] = A @ Bw^T ; EPI: 0 = +bias(opt), 1 = +bias & leaky(0.1)
template <int EPI>
__global__ __launch_bounds__(256, 3)
void gemm_p(const float* __restrict__ A, int lda,
            const float* __restrict__ Bw, int ldb,
            const float* __restrict__ bias,
            float* __restrict__ C, int ldc, int Kc)
{
    __shared__ __align__(16) float As[3 * ASTG];
    __shared__ __align__(16) float Bs[3 * BSTG];

    const int bm = blockIdx.y * TBM;
    const int bn = blockIdx.x * TBN;
    const int tid  = threadIdx.x;
    const int lane = tid & 31;
    const int w    = tid >> 5;
    const int wm = (w & 3) * 32;
    const int wn = (w >> 2) * 32;
    const int gr = lane >> 2;
    const int gc = lane & 3;

    const uint32_t sA = smem_u32(As);
    const uint32_t sB = smem_u32(Bs);

    float acc[2][4][4] = {};

    LOAD_AB(A, lda, Bw, ldb, 0, sA, sB);
    asm volatile("cp.async.commit_group;\n");
    LOAD_AB(A, lda, Bw, ldb, 1, sA + ASTG * 4, sB + BSTG * 4);
    asm volatile("cp.async.commit_group;\n");

    for (int kc = 0; kc < Kc; kc++) {
        asm volatile("cp.async.wait_group 1;\n");
        __syncthreads();
        int sn = (kc + 2) % 3;
        if (kc + 2 < Kc)
            LOAD_AB(A, lda, Bw, ldb, kc + 2, sA + sn * ASTG * 4, sB + sn * BSTG * 4);
        asm volatile("cp.async.commit_group;\n");

        int s = kc % 3;
        const float* Asb = As + s * ASTG;
        const float* Bsb = Bs + s * BSTG;
        COMPUTE_CHUNK(Asb, Bsb, acc);
    }

    #pragma unroll
    for (int mt = 0; mt < 2; mt++) {
        #pragma unroll
        for (int half = 0; half < 2; half++) {
            int row = bm + wm + mt * 16 + gr + half * 8;
            #pragma unroll
            for (int nt = 0; nt < 4; nt++) {
                int col = bn + wn + nt * 8 + gc * 2;
                if (col >= SP) continue;
                float v0 = acc[mt][nt][half * 2 + 0];
                float v1 = acc[mt][nt][half * 2 + 1];
                float2 o2 = make_float2(0.0f, 0.0f);
                if (col < HH) {
                    if (EPI == 0) {
                        if (bias) { v0 += bias[col]; v1 += bias[col + 1]; }
                        o2 = make_float2(v0, v1);
                    } else {
                        v0 += bias[col]; v1 += bias[col + 1];
                        o2.x = (v0 > 0.0f) ? v0 : 0.1f * v0;
                        o2.y = (v1 > 0.0f) ? v1 : 0.1f * v1;
                    }
                }
                *reinterpret_cast<float2*>(C + (size_t)row * ldc + col) = o2;
            }
        }
    }
}

// ---------------- dual GEMM + fused GRU gate epilogue ---------------------------
// acc1 = sh@Wz2^T, acc2 = sg@Wh2^T; h = ((1-z)*sh + z*tanh(xh+acc2)), z=sigm(xz+acc1)
// dynamic smem: 2 stages x [A1 | A2 | B1 | B2]
#define DSTG (2 * ASTG + 2 * BSTG)   // floats per stage (7680)

__global__ __launch_bounds__(256, 2)
void gemm_dual(const float* __restrict__ A1, const float* __restrict__ A2,
               const float* __restrict__ B1, const float* __restrict__ B2,
               const float* __restrict__ xz, const float* __restrict__ xh,
               float* __restrict__ hout)
{
    extern __shared__ __align__(16) float ds[];

    const int bm = blockIdx.y * TBM;
    const int bn = blockIdx.x * TBN;
    const int tid  = threadIdx.x;
    const int lane = tid & 31;
    const int w    = tid >> 5;
    const int wm = (w & 3) * 32;
    const int wn = (w >> 2) * 32;
    const int gr = lane >> 2;
    const int gc = lane & 3;

    const uint32_t s0 = smem_u32(ds);

    float acc1[2][4][4] = {};
    float acc2[2][4][4] = {};

    const int Kc = SP / TBK;   // 29

    #define DLOAD(kc_, s_)                                                      \
        do {                                                                    \
            uint32_t b_ = s0 + (s_) * DSTG * 4;                                 \
            LOAD_AB(A1, SP, B1, SP, kc_, b_, b_ + 2 * ASTG * 4);                \
            LOAD_AB(A2, SP, B2, SP, kc_, b_ + ASTG * 4, b_ + (2 * ASTG + BSTG) * 4); \
        } while (0)

    DLOAD(0, 0);
    asm volatile("cp.async.commit_group;\n");

    for (int kc = 0; kc < Kc; kc++) {
        if (kc + 1 < Kc) DLOAD(kc + 1, (kc + 1) & 1);
        asm volatile("cp.async.commit_group;\n");
        asm volatile("cp.async.wait_group 1;\n");
        __syncthreads();

        const float* base = ds + (kc & 1) * DSTG;
        COMPUTE_CHUNK(base,            base + 2 * ASTG,        acc1);
        COMPUTE_CHUNK(base + ASTG,     base + 2 * ASTG + BSTG, acc2);
        __syncthreads();
    }

    #pragma unroll
    for (int mt = 0; mt < 2; mt++) {
        #pragma unroll
        for (int half = 0; half < 2; half++) {
            int row = bm + wm + mt * 16 + gr + half * 8;
            #pragma unroll
            for (int nt = 0; nt < 4; nt++) {
                int col = bn + wn + nt * 8 + gc * 2;
                if (col >= SP) continue;
                float2 o2 = make_float2(0.0f, 0.0f);
                if (col < HH && row != 0) {
                    size_t o = (size_t)row * SP + col;
                    float2 xzv = *reinterpret_cast<const float2*>(xz + o);
                    float2 xhv = *reinterpret_cast<const float2*>(xh + o);
                    float2 shv = *reinterpret_cast<const float2*>(A1 + o);
                    float z0 = sigmoid_(xzv.x + acc1[mt][nt][half * 2 + 0]);
                    float z1 = sigmoid_(xzv.y + acc1[mt][nt][half * 2 + 1]);
                    float p0 = tanh_(xhv.x + acc2[mt][nt][half * 2 + 0]);
                    float p1 = tanh_(xhv.y + acc2[mt][nt][half * 2 + 1]);
                    o2.x = (1.0f - z0) * shv.x + z0 * p0;
                    o2.y = (1.0f - z1) * shv.y + z1 * p1;
                }
                *reinterpret_cast<float2*>(hout + (size_t)row * SP + col) = o2;
            }
        }
    }
    #undef DLOAD
}

// ---------------- weight prep: round to tf32, repack zero-padded ---------------
__global__ void prep_w(const float* __restrict__ Wz, const float* __restrict__ Wr,
                       const float* __restrict__ Ur, const float* __restrict__ Wh,
                       const float* __restrict__ D1, const float* __restrict__ D2,
                       float* __restrict__ wz1, float* __restrict__ wz2,
                       float* __restrict__ wr,  float* __restrict__ ur,
                       float* __restrict__ wh1, float* __restrict__ wh2,
                       float* __restrict__ d1w, float* __restrict__ d2w)
{
    int mat = blockIdx.y;
    int idx = blockIdx.x * 256 + threadIdx.x;
    if (mat < 7) {
        if (idx >= WPAD * SP) return;
        int r = idx / SP, c = idx % SP;
        float v = 0.0f;
        if (r < HH && c < HH) {
            switch (mat) {
                case 0: v = Wz[r * HH2 + c];      break;
                case 1: v = Wz[r * HH2 + HH + c]; break;
                case 2: v = Wr[r * HH + c];       break;
                case 3: v = Ur[r * HH + c];       break;
                case 4: v = Wh[r * HH2 + c];      break;
                case 5: v = Wh[r * HH2 + HH + c]; break;
                case 6: v = D2[r * HH + c];       break;
            }
            v = tf32r(v);
        }
        switch (mat) {
            case 0: wz1[idx] = v; break;
            case 1: wz2[idx] = v; break;
            case 2: wr [idx] = v; break;
            case 3: ur [idx] = v; break;
            case 4: wh1[idx] = v; break;
            case 5: wh2[idx] = v; break;
            case 6: d2w[idx] = v; break;
        }
    } else {
        if (idx >= WPAD * SP2) return;
        int r = idx / SP2, c = idx % SP2;
        float v = 0.0f;
        if (r < HH) {
            if (c < HH)                      v = D1[r * HH2 + c];
            else if (c >= SP && c - SP < HH) v = D1[r * HH2 + HH + (c - SP)];
            v = tf32r(v);
        }
        d1w[idx] = v;
    }
}

// ---------------- x = emb[fnode[fmess]], zero-padded ---------------------------
__global__ void x_gather(const float* __restrict__ emb,
                         const int* __restrict__ fnode,
                         const int* __restrict__ fmess,
                         float* __restrict__ x)
{
    int m = blockIdx.x;
    int j = threadIdx.x * 2;
    if (j >= SP) return;
    float2 v = make_float2(0.0f, 0.0f);
    if (m < NM && j < HH) {
        int e = fnode[fmess[m]];
        v = *reinterpret_cast<const float2*>(emb + (size_t)e * HH + j);
    }
    *reinterpret_cast<float2*>(x + (size_t)m * SP + j) = v;
}

// ---------------- first GRU step (h0 = 0) --------------------------------------
__global__ void init_h(const float* __restrict__ xz, const float* __restrict__ xh,
                       float* __restrict__ h)
{
    int m = blockIdx.x;
    int j = threadIdx.x * 2;
    if (j >= SP) return;
    size_t o = (size_t)m * SP + j;
    float2 v = make_float2(0.0f, 0.0f);
    if (m > 0 && m < NM && j < HH) {
        float2 a = *reinterpret_cast<const float2*>(xz + o);
        float2 b = *reinterpret_cast<const float2*>(xh + o);
        v.x = sigmoid_(a.x) * tanh_(b.x);
        v.y = sigmoid_(a.y) * tanh_(b.y);
    }
    *reinterpret_cast<float2*>(h + o) = v;
}

// ---------------- gather: sum_h, sum_gh (r fused), float4 ----------------------
__global__ void gather_k(const float* __restrict__ h, const float* __restrict__ hU,
                         const float* __restrict__ xr, const int* __restrict__ mg,
                         float* __restrict__ sumh, float* __restrict__ sumgh)
{
    int m = blockIdx.x;
    int j = threadIdx.x * 4;
    if (j >= SP) return;
    size_t o = (size_t)m * SP + j;
    float4 xr4 = *reinterpret_cast<const float4*>(xr + o);
    float4 sh4 = make_float4(0.f, 0.f, 0.f, 0.f);
    float4 sg4 = make_float4(0.f, 0.f, 0.f, 0.f);
    #pragma unroll
    for (int k = 0; k < KN; k++) {
        int idx = mg[m * KN + k];
        size_t q = (size_t)idx * SP + j;
        float4 h4  = *reinterpret_cast<const float4*>(h  + q);
        float4 hu4 = *reinterpret_cast<const float4*>(hU + q);
        sh4.x += h4.x; sh4.y += h4.y; sh4.z += h4.z; sh4.w += h4.w;
        sg4.x += sigmoid_(xr4.x + hu4.x) * h4.x;
        sg4.y += sigmoid_(xr4.y + hu4.y) * h4.y;
        sg4.z += sigmoid_(xr4.z + hu4.z) * h4.z;
        sg4.w += sigmoid_(xr4.w + hu4.w) * h4.w;
    }
    *reinterpret_cast<float4*>(sumh  + o) = sh4;
    *reinterpret_cast<float4*>(sumgh + o) = sg4;
}

// ---------------- root vectors: [emb | pad | sum | pad], stride 928 ------------
__global__ void root_k(const float* __restrict__ emb, const int* __restrict__ fnode,
                       const int* __restrict__ ridx, const int* __restrict__ ng,
                       const float* __restrict__ h, float* __restrict__ root)
{
    int b = blockIdx.x;
    int node = ridx[b];
    int e = fnode[node];
    for (int j = threadIdx.x; j < SP2; j += blockDim.x) {
        float v = 0.0f;
        if (j < HH) {
            v = emb[(size_t)e * HH + j];
        } else if (j >= SP && j - SP < HH) {
            int c = j - SP;
            float s = 0.0f;
            #pragma unroll
            for (int k = 0; k < KN; k++) {
                int mi = ng[node * KN + k];
                s += h[(size_t)mi * SP + c];
            }
            v = s;
        }
        root[(size_t)b * SP2 + j] = v;
    }
}

// ---------------- final D3 dot product -----------------------------------------
__global__ void d3_k(const float* __restrict__ d2, const float* __restrict__ w,
                     const float* __restrict__ bb, float* __restrict__ out)
{
    int b = blockIdx.x;
    float s = 0.0f;
    for (int i = threadIdx.x; i < HH; i += blockDim.x)
        s += d2[(size_t)b * SP + i] * w[i];
    __shared__ float red[128];
    red[threadIdx.x] = s;
    __syncthreads();
    for (int st = 64; st > 0; st >>= 1) {
        if (threadIdx.x < st) red[threadIdx.x] += red[threadIdx.x + st];
        __syncthreads();
    }
    if (threadIdx.x == 0) out[b] = red[0] + bb[0];
}

// ---------------- launch ---------------------------------------------------------
extern "C" void kernel_launch(void* const* d_in, const int* in_sizes, int n_in,
                              void* d_out, int out_size)
{
    const int*   fnode      = (const int*)d_in[0];
    const int*   fmess      = (const int*)d_in[1];
    const int*   node_graph = (const int*)d_in[2];
    const int*   mess_graph = (const int*)d_in[3];
    const int*   root_idx   = (const int*)d_in[4];
    const float* emb        = (const float*)d_in[5];
    const float* Wz         = (const float*)d_in[6];
    const float* Wz_b       = (const float*)d_in[7];
    const float* Wr         = (const float*)d_in[8];
    const float* Ur         = (const float*)d_in[9];
    const float* Ur_b       = (const float*)d_in[10];
    const float* Wh         = (const float*)d_in[11];
    const float* Wh_b       = (const float*)d_in[12];
    const float* D1w        = (const float*)d_in[13];
    const float* D1b        = (const float*)d_in[14];
    const float* D2w        = (const float*)d_in[15];
    const float* D2b        = (const float*)d_in[16];
    const float* D3w        = (const float*)d_in[17];
    const float* D3b        = (const float*)d_in[18];
    float* out = (float*)d_out;

    float *x, *xz, *xr, *xh, *hA, *hB, *hU, *sh, *sg, *root, *d1, *d2;
    float *wz1, *wz2, *wr, *ur, *wh1, *wh2, *d1w, *d2w;
    cudaGetSymbolAddress((void**)&x,    g_x);
    cudaGetSymbolAddress((void**)&xz,   g_xz);
    cudaGetSymbolAddress((void**)&xr,   g_xr);
    cudaGetSymbolAddress((void**)&xh,   g_xh);
    cudaGetSymbolAddress((void**)&hA,   g_hA);
    cudaGetSymbolAddress((void**)&hB,   g_hB);
    cudaGetSymbolAddress((void**)&hU,   g_hU);
    cudaGetSymbolAddress((void**)&sh,   g_sh);
    cudaGetSymbolAddress((void**)&sg,   g_sg);
    cudaGetSymbolAddress((void**)&root, g_root);
    cudaGetSymbolAddress((void**)&d1,   g_d1);
    cudaGetSymbolAddress((void**)&d2,   g_d2);
    cudaGetSymbolAddress((void**)&wz1,  g_wz1);
    cudaGetSymbolAddress((void**)&wz2,  g_wz2);
    cudaGetSymbolAddress((void**)&wr,   g_wr);
    cudaGetSymbolAddress((void**)&ur,   g_ur);
    cudaGetSymbolAddress((void**)&wh1,  g_wh1);
    cudaGetSymbolAddress((void**)&wh2,  g_wh2);
    cudaGetSymbolAddress((void**)&d1w,  g_d1w);
    cudaGetSymbolAddress((void**)&d2w,  g_d2w);

    const int KC1 = SP / TBK;    // 29
    const int KC2 = SP2 / TBK;   // 58
    const int DUAL_SMEM = 2 * DSTG * 4;   // 61440 bytes

    cudaFuncSetAttribute(gemm_dual, cudaFuncAttributeMaxDynamicSharedMemorySize,
                         DUAL_SMEM);

    // weight prep (round + repack, zero-padded)
    dim3 pgrid((WPAD * SP2 + 255) / 256, 8);
    prep_w<<<pgrid, 256>>>(Wz, Wr, Ur, Wh, D1w, D2w,
                           wz1, wz2, wr, ur, wh1, wh2, d1w, d2w);

    // x = emb[fnode[fmess]]
    x_gather<<<MPAD, SP / 2>>>(emb, fnode, fmess, x);

    dim3 ggrid(SP / TBN + (SP % TBN ? 1 : 0), MPAD / TBM);   // 8 x 47
    dim3 blk(256);

    // Loop-invariant x-projections
    gemm_p<0><<<ggrid, blk>>>(x, SP, wz1, SP, Wz_b, xz, SP, KC1);
    gemm_p<0><<<ggrid, blk>>>(x, SP, wr,  SP, Ur_b, xr, SP, KC1);
    gemm_p<0><<<ggrid, blk>>>(x, SP, wh1, SP, Wh_b, xh, SP, KC1);

    // Step 1 specialized for h0 = 0
    init_h<<<MPAD, SP / 2>>>(xz, xh, hA);

    float* hcur = hA;
    float* hnxt = hB;
    for (int it = 0; it < NDEPTH - 1; ++it) {
        gemm_p<0><<<ggrid, blk>>>(hcur, SP, ur, SP, nullptr, hU, SP, KC1);
        gather_k<<<NM, 128>>>(hcur, hU, xr, mess_graph, sh, sg);
        gemm_dual<<<ggrid, blk, DUAL_SMEM>>>(sh, sg, wz2, wh2, xz, xh, hnxt);
        float* t = hcur; hcur = hnxt; hnxt = t;
    }

    // Root vectors + discriminator MLP
    root_k<<<NB, 256>>>(emb, fnode, root_idx, node_graph, hcur, root);

    dim3 dgrid(8, NB / TBM);   // 8 x 2
    gemm_p<1><<<dgrid, blk>>>(root, SP2, d1w, SP2, D1b, d1, SP, KC2);
    gemm_p<1><<<dgrid, blk>>>(d1,   SP,  d2w, SP,  D2b, d2, SP, KC1);
    d3_k<<<NB, 128>>>(d2, D3w, D3b, out);
}